// round 6
// baseline (speedup 1.0000x reference)
#include <cuda_runtime.h>
#include <math.h>

// Problem dims (fixed by the reference)
namespace cfg {
constexpr int V = 32000, E = 512, H = 1024, S = 50, B = 64, T = 10;
constexpr int H2 = 2 * H, H3 = 3 * H;
constexpr int KSPLIT = 4;   // split-K for the fused GRU step
}
using namespace cfg;

// ---------------- device scratch (no allocations allowed) ----------------
__device__ float g_xs[T * B * E];          // gathered embeddings  [T*B, E]
__device__ float g_gi[T * B * H3];         // x @ w_ih^T + b_ih    [T*B, 3H]
__device__ float g_ghp[KSPLIT * B * H3];   // split-K partials of h @ w_hh^T
__device__ float g_hs[T * B * H];          // GRU hidden states    [T, B, H]
__device__ float g_uk[B * S * H];          // enc @ ua_w^T + ua_b, rows in (s*B+b) order
__device__ float g_wq[T * B * H];          // hs @ wa_w^T + wa_b   [T*B, H]
__device__ float g_sc[T * B * S];          // scores / weights     [T*B, S]
__device__ int   g_cnt[T];                 // per-step barrier counters (zeroed each call)

// ---------------- small intrinsics ----------------
__device__ __forceinline__ float tanha(float x) {
    float y;
    asm("tanh.approx.f32 %0, %1;" : "=f"(y) : "f"(x));
    return y;
}
// RNA round-to-nearest for tf32: add half-ULP of the 10-bit mantissa.
__device__ __forceinline__ unsigned rna(float f) {
    return __float_as_uint(f) + 0x1000u;
}
__device__ __forceinline__ void mma8(float* c, const unsigned* a, const unsigned* b) {
    asm volatile(
        "mma.sync.aligned.m16n8k8.row.col.f32.tf32.tf32.f32 "
        "{%0,%1,%2,%3}, {%4,%5,%6,%7}, {%8,%9}, {%0,%1,%2,%3};"
        : "+f"(c[0]), "+f"(c[1]), "+f"(c[2]), "+f"(c[3])
        : "r"(a[0]), "r"(a[1]), "r"(a[2]), "r"(a[3]), "r"(b[0]), "r"(b[1]));
}
__device__ __forceinline__ void cp16(float* smem_dst, const float* gptr) {
    unsigned s = (unsigned)__cvta_generic_to_shared(smem_dst);
    asm volatile("cp.async.cg.shared.global [%0], [%1], 16;\n" :: "r"(s), "l"(gptr));
}

// ---------------- tf32 tensor-core GEMM (cp.async double-buffered) ---------
// C[m][n] = (bias?bias[n]:0) + sum_k A[m][k]*W[n][k]; A [M,K], W [N,K] row-major.
template <int BM, int BN, int WM, int WN>
__global__ void __launch_bounds__(WM * WN * 32, 2)
k_gemm_tf32(const float* __restrict__ A, const float* __restrict__ W,
            const float* __restrict__ bias, float* __restrict__ C,
            int M, int N, int K) {
    constexpr int BK = 32;
    constexpr int NT = WM * WN * 32;
    constexpr int TM = BM / WM;
    constexpr int TN = BN / WN;
    constexpr int MM = TM / 16;
    constexpr int MN = TN / 8;
    constexpr int LDSR = BK + 4;
    constexpr int A_LD = BM * (BK / 4) / NT;
    constexpr int B_LD = BN * (BK / 4) / NT;

    extern __shared__ float sm[];
    float* Asm = sm;                      // [2][BM*LDSR]
    float* Bsm = sm + 2 * BM * LDSR;      // [2][BN*LDSR]

    const int tid = threadIdx.x;
    const int warp = tid >> 5, lane = tid & 31;
    const int wm = warp / WN, wn = warp % WN;
    const int g = lane >> 2, tg = lane & 3;
    const int bm = blockIdx.y * BM, bn = blockIdx.x * BN;

    float acc[MM][MN][4];
#pragma unroll
    for (int im = 0; im < MM; im++)
#pragma unroll
        for (int in = 0; in < MN; in++)
#pragma unroll
            for (int q = 0; q < 4; q++) acc[im][in][q] = 0.f;

    auto issue = [&](int k0, int buf) {
        float* as = Asm + buf * BM * LDSR;
        float* bs = Bsm + buf * BN * LDSR;
#pragma unroll
        for (int i = 0; i < A_LD; i++) {
            int idx = tid + i * NT;
            int r = idx >> 3, kq = idx & 7;
            cp16(&as[r * LDSR + kq * 4], A + (size_t)(bm + r) * K + k0 + kq * 4);
        }
#pragma unroll
        for (int i = 0; i < B_LD; i++) {
            int idx = tid + i * NT;
            int r = idx >> 3, kq = idx & 7;
            cp16(&bs[r * LDSR + kq * 4], W + (size_t)(bn + r) * K + k0 + kq * 4);
        }
        asm volatile("cp.async.commit_group;\n" ::);
    };

    issue(0, 0);
    const int KT = K / BK;
    for (int kt = 0; kt < KT; kt++) {
        if (kt + 1 < KT) {
            issue((kt + 1) * BK, (kt + 1) & 1);
            asm volatile("cp.async.wait_group 1;\n" ::);
        } else {
            asm volatile("cp.async.wait_group 0;\n" ::);
        }
        __syncthreads();

        const float* as = Asm + (kt & 1) * BM * LDSR;
        const float* bs = Bsm + (kt & 1) * BN * LDSR;
#pragma unroll
        for (int ks = 0; ks < 4; ks++) {
            const int kk = ks * 8;
            unsigned af[MM][4], bf[MN][2];
#pragma unroll
            for (int im = 0; im < MM; im++) {
                int m0 = wm * TM + im * 16;
                af[im][0] = rna(as[(m0 + g) * LDSR + kk + tg]);
                af[im][1] = rna(as[(m0 + 8 + g) * LDSR + kk + tg]);
                af[im][2] = rna(as[(m0 + g) * LDSR + kk + 4 + tg]);
                af[im][3] = rna(as[(m0 + 8 + g) * LDSR + kk + 4 + tg]);
            }
#pragma unroll
            for (int in = 0; in < MN; in++) {
                int n0 = wn * TN + in * 8;
                bf[in][0] = rna(bs[(n0 + g) * LDSR + kk + tg]);
                bf[in][1] = rna(bs[(n0 + g) * LDSR + kk + 4 + tg]);
            }
#pragma unroll
            for (int im = 0; im < MM; im++)
#pragma unroll
                for (int in = 0; in < MN; in++)
                    mma8(acc[im][in], af[im], bf[in]);
        }
        __syncthreads();
    }

#pragma unroll
    for (int im = 0; im < MM; im++) {
        int row0 = bm + wm * TM + im * 16 + g;
#pragma unroll
        for (int in = 0; in < MN; in++) {
            int col = bn + wn * TN + in * 8 + 2 * tg;
            float2 bb = *(const float2*)(bias + col);
            float* c = acc[im][in];
            *(float2*)(C + (size_t)row0 * N + col) = make_float2(c[0] + bb.x, c[1] + bb.y);
            *(float2*)(C + (size_t)(row0 + 8) * N + col) = make_float2(c[2] + bb.x, c[3] + bb.y);
        }
    }
}

// ---------------- fused GRU step: split-K GEMM + global barrier + gate ------
// Grid: dim3(H3/128, 1, KSPLIT) = (24,1,4) = 96 blocks, 256 threads.
// Phase 1: partial[z] = hprev @ w_hh^T over K slice z (BM=64,BN=128,WM=2,WN=4).
// Phase 2 (after device-wide barrier): gate h_new = (1-z)*tanh(in+r*hn)+z*h.
__global__ void __launch_bounds__(256)
k_gru_step(const float* __restrict__ hprev, const float* __restrict__ whh,
           const float* __restrict__ gi, const float* __restrict__ b_hh_,
           float* __restrict__ part, float* __restrict__ hnew, int step) {
    constexpr int BM = 64, BN = 128, WM = 2, WN = 4;
    constexpr int BK = 32, NT = 256;
    constexpr int TM = BM / WM, TN = BN / WN;
    constexpr int MM = TM / 16, MN = TN / 8;
    constexpr int LDSR = BK + 4;
    constexpr int A_LD = BM * (BK / 4) / NT;   // 2
    constexpr int B_LD = BN * (BK / 4) / NT;   // 4
    constexpr int NBLK = (H3 / BN) * KSPLIT;   // 96
    const int klen = H / KSPLIT;               // 256

    extern __shared__ float sm[];
    float* Asm = sm;
    float* Bsm = sm + 2 * BM * LDSR;

    const int tid = threadIdx.x;
    const int warp = tid >> 5, lane = tid & 31;
    const int wm = warp / WN, wn = warp % WN;
    const int g = lane >> 2, tg = lane & 3;
    const int bn = blockIdx.x * BN;
    const int kstart = blockIdx.z * klen;
    float* C = part + (size_t)blockIdx.z * B * H3;

    float acc[MM][MN][4];
#pragma unroll
    for (int im = 0; im < MM; im++)
#pragma unroll
        for (int in = 0; in < MN; in++)
#pragma unroll
            for (int q = 0; q < 4; q++) acc[im][in][q] = 0.f;

    auto issue = [&](int k0, int buf) {
        float* as = Asm + buf * BM * LDSR;
        float* bs = Bsm + buf * BN * LDSR;
#pragma unroll
        for (int i = 0; i < A_LD; i++) {
            int idx = tid + i * NT;
            int r = idx >> 3, kq = idx & 7;
            cp16(&as[r * LDSR + kq * 4], hprev + (size_t)r * H + kstart + k0 + kq * 4);
        }
#pragma unroll
        for (int i = 0; i < B_LD; i++) {
            int idx = tid + i * NT;
            int r = idx >> 3, kq = idx & 7;
            cp16(&bs[r * LDSR + kq * 4], whh + (size_t)(bn + r) * H + kstart + k0 + kq * 4);
        }
        asm volatile("cp.async.commit_group;\n" ::);
    };

    issue(0, 0);
    const int KT = klen / BK;
    for (int kt = 0; kt < KT; kt++) {
        if (kt + 1 < KT) {
            issue((kt + 1) * BK, (kt + 1) & 1);
            asm volatile("cp.async.wait_group 1;\n" ::);
        } else {
            asm volatile("cp.async.wait_group 0;\n" ::);
        }
        __syncthreads();

        const float* as = Asm + (kt & 1) * BM * LDSR;
        const float* bs = Bsm + (kt & 1) * BN * LDSR;
#pragma unroll
        for (int ks = 0; ks < 4; ks++) {
            const int kk = ks * 8;
            unsigned af[MM][4], bf[MN][2];
#pragma unroll
            for (int im = 0; im < MM; im++) {
                int m0 = wm * TM + im * 16;
                af[im][0] = rna(as[(m0 + g) * LDSR + kk + tg]);
                af[im][1] = rna(as[(m0 + 8 + g) * LDSR + kk + tg]);
                af[im][2] = rna(as[(m0 + g) * LDSR + kk + 4 + tg]);
                af[im][3] = rna(as[(m0 + 8 + g) * LDSR + kk + 4 + tg]);
            }
#pragma unroll
            for (int in = 0; in < MN; in++) {
                int n0 = wn * TN + in * 8;
                bf[in][0] = rna(bs[(n0 + g) * LDSR + kk + tg]);
                bf[in][1] = rna(bs[(n0 + g) * LDSR + kk + 4 + tg]);
            }
#pragma unroll
            for (int im = 0; im < MM; im++)
#pragma unroll
                for (int in = 0; in < MN; in++)
                    mma8(acc[im][in], af[im], bf[in]);
        }
        __syncthreads();
    }

    // write partials
#pragma unroll
    for (int im = 0; im < MM; im++) {
        int row0 = wm * TM + im * 16 + g;
#pragma unroll
        for (int in = 0; in < MN; in++) {
            int col = bn + wn * TN + in * 8 + 2 * tg;
            float* c = acc[im][in];
            *(float2*)(C + (size_t)row0 * H3 + col) = make_float2(c[0], c[1]);
            *(float2*)(C + (size_t)(row0 + 8) * H3 + col) = make_float2(c[2], c[3]);
        }
    }

    // -------- device-wide barrier (all 96 blocks co-resident by capacity) ---
    __syncthreads();            // all stores in this block issued
    if (tid == 0) {
        __threadfence();        // partials visible device-wide
        atomicAdd(&g_cnt[step], 1);
        while (atomicAdd(&g_cnt[step], 0) < NBLK) __nanosleep(64);
    }
    __syncthreads();

    // -------- gate phase: B*H elements over 96*256 threads -------------------
    const int gtid = (blockIdx.z * gridDim.x + blockIdx.x) * NT + tid;
    const int nthreads = NBLK * NT;   // 24576
    for (int idx = gtid; idx < B * H; idx += nthreads) {
        int b = idx / H, j = idx % H;
        float hr = b_hh_[j], hz = b_hh_[H + j], hn = b_hh_[2 * H + j];
#pragma unroll
        for (int z = 0; z < KSPLIT; z++) {
            const float* p = part + (size_t)z * B * H3 + (size_t)b * H3;
            hr += p[j];
            hz += p[H + j];
            hn += p[2 * H + j];
        }
        const float* gib = gi + (size_t)b * H3;
        float ir = gib[j], iz = gib[H + j], in_ = gib[2 * H + j];
        float r = 1.f / (1.f + expf(-(ir + hr)));
        float z_ = 1.f / (1.f + expf(-(iz + hz)));
        float n = tanhf(in_ + r * hn);
        hnew[idx] = (1.f - z_) * n + z_ * hprev[idx];
    }
}

// ---------------- elementwise / attention kernels ----------------

__global__ void k_gather(const int* __restrict__ target,
                         const float* __restrict__ emb,
                         float* __restrict__ xs) {
    int idx = blockIdx.x * 256 + threadIdx.x;
    if (blockIdx.x == 0 && threadIdx.x < T) g_cnt[threadIdx.x] = 0;  // reset barriers
    if (idx >= T * B * E) return;
    int e = idx % E;
    int m = idx / E;
    int b = m % B;
    int t = m / B;
    int tok = (t == 0) ? 0 : target[b * T + (t - 1)];
    xs[idx] = emb[tok * E + e];
}

// scores: grid (B, 4); wq[T][H] staged in smem; uk rows are in (s*B+b) order.
__global__ void k_scores(const float* __restrict__ wq, const float* __restrict__ uk,
                         const float* __restrict__ va_w, const float* __restrict__ va_b,
                         float* __restrict__ scores) {
    __shared__ float wqs[T][H];  // 40 KB
    int b = blockIdx.x, q = blockIdx.y;
    int tid = threadIdx.x;
    for (int i = tid; i < T * H; i += 256) {
        wqs[0][i] = wq[(size_t)(i / H * B + b) * H + (i % H)];
    }
    __syncthreads();

    int warp = tid >> 5, lane = tid & 31;
    float vb = va_b[0];
    for (int s = q * 8 + warp; s < S; s += 32) {
        const float4* ukr = (const float4*)(uk + (size_t)(s * B + b) * H);
        const float4* vw = (const float4*)va_w;
        float acc[T];
#pragma unroll
        for (int t = 0; t < T; t++) acc[t] = 0.f;
#pragma unroll
        for (int i = 0; i < H / 128; i++) {
            float4 u = ukr[lane + i * 32];
            float4 v = vw[lane + i * 32];
#pragma unroll
            for (int t = 0; t < T; t++) {
                float4 w = *(const float4*)&wqs[t][(lane + i * 32) * 4];
                float a = acc[t];
                a = fmaf(v.x, tanha(w.x + u.x), a);
                a = fmaf(v.y, tanha(w.y + u.y), a);
                a = fmaf(v.z, tanha(w.z + u.z), a);
                a = fmaf(v.w, tanha(w.w + u.w), a);
                acc[t] = a;
            }
        }
#pragma unroll
        for (int t = 0; t < T; t++) {
#pragma unroll
            for (int o = 16; o; o >>= 1) acc[t] += __shfl_xor_sync(0xffffffffu, acc[t], o);
            if (lane == 0) scores[(size_t)(t * B + b) * S + s] = acc[t] + vb;
        }
    }
}

// softmax over S (=50) per row; one warp per (t,b)
__global__ void k_softmax(float* __restrict__ scores) {
    int row = (blockIdx.x * blockDim.x + threadIdx.x) >> 5;
    int lane = threadIdx.x & 31;
    if (row >= T * B) return;
    float* p = scores + (size_t)row * S;
    float v0 = (lane < S) ? p[lane] : -1e30f;
    float v1 = (lane + 32 < S) ? p[lane + 32] : -1e30f;
    float m = fmaxf(v0, v1);
#pragma unroll
    for (int o = 16; o; o >>= 1) m = fmaxf(m, __shfl_xor_sync(0xffffffffu, m, o));
    float e0 = (lane < S) ? expf(v0 - m) : 0.f;
    float e1 = (lane + 32 < S) ? expf(v1 - m) : 0.f;
    float sum = e0 + e1;
#pragma unroll
    for (int o = 16; o; o >>= 1) sum += __shfl_xor_sync(0xffffffffu, sum, o);
    float inv = 1.f / sum;
    if (lane < S) p[lane] = e0 * inv;
    if (lane + 32 < S) p[lane + 32] = e1 * inv;
}

// context + log_softmax: one block per b; enc rows (s*B+b) streamed once for all T.
__global__ void k_context(const float* __restrict__ weights,
                          const float* __restrict__ enc,
                          float* __restrict__ out) {
    int b = blockIdx.x;
    int tid = threadIdx.x;
    __shared__ float w[T][S];
    __shared__ float red[8];

    for (int i = tid; i < T * S; i += 256) {
        int t = i / S, s = i % S;
        w[t][s] = weights[(size_t)(t * B + b) * S + s];
    }
    __syncthreads();

    float c[T][8];
#pragma unroll
    for (int t = 0; t < T; t++)
#pragma unroll
        for (int i = 0; i < 8; i++) c[t][i] = 0.f;

    for (int s = 0; s < S; s++) {
        const float* kr = enc + (size_t)(s * B + b) * H2;
        float4 k0 = *(const float4*)(kr + tid * 8);
        float4 k1 = *(const float4*)(kr + tid * 8 + 4);
        float kv[8] = {k0.x, k0.y, k0.z, k0.w, k1.x, k1.y, k1.z, k1.w};
#pragma unroll
        for (int t = 0; t < T; t++) {
            float ws = w[t][s];
#pragma unroll
            for (int i = 0; i < 8; i++) c[t][i] = fmaf(ws, kv[i], c[t][i]);
        }
    }

    for (int t = 0; t < T; t++) {
        float m = c[t][0];
#pragma unroll
        for (int i = 1; i < 8; i++) m = fmaxf(m, c[t][i]);
#pragma unroll
        for (int o = 16; o; o >>= 1) m = fmaxf(m, __shfl_xor_sync(0xffffffffu, m, o));
        if ((tid & 31) == 0) red[tid >> 5] = m;
        __syncthreads();
        if (tid == 0) {
            float mm = red[0];
            for (int i = 1; i < 8; i++) mm = fmaxf(mm, red[i]);
            red[0] = mm;
        }
        __syncthreads();
        m = red[0];
        __syncthreads();

        float sum = 0.f;
#pragma unroll
        for (int i = 0; i < 8; i++) sum += expf(c[t][i] - m);
#pragma unroll
        for (int o = 16; o; o >>= 1) sum += __shfl_xor_sync(0xffffffffu, sum, o);
        if ((tid & 31) == 0) red[tid >> 5] = sum;
        __syncthreads();
        if (tid == 0) {
            float ss = 0.f;
            for (int i = 1; i < 8; i++) ss += red[i];
            red[0] += ss;
        }
        __syncthreads();
        float lse = m + logf(red[0]);
        __syncthreads();

        float* o_ = out + (size_t)(b * T + t) * H2 + tid * 8;
        *(float4*)o_ = make_float4(c[t][0] - lse, c[t][1] - lse, c[t][2] - lse, c[t][3] - lse);
        *(float4*)(o_ + 4) = make_float4(c[t][4] - lse, c[t][5] - lse, c[t][6] - lse, c[t][7] - lse);
    }
}

__global__ void k_hlast(const float* __restrict__ src, float* __restrict__ dst) {
    int idx = blockIdx.x * 256 + threadIdx.x;
    if (idx < B * H) dst[idx] = src[idx];
}

// ---------------- launch (single default stream, deterministic) -------------
extern "C" void kernel_launch(void* const* d_in, const int* in_sizes, int n_in,
                              void* d_out, int out_size) {
    const float* enc    = (const float*)d_in[0];
    const float* hidden = (const float*)d_in[1];
    const int*   target = (const int*)d_in[2];
    const float* emb    = (const float*)d_in[3];
    const float* w_ih   = (const float*)d_in[4];
    const float* w_hh   = (const float*)d_in[5];
    const float* b_ih   = (const float*)d_in[6];
    const float* b_hh   = (const float*)d_in[7];
    const float* wa_w   = (const float*)d_in[8];
    const float* wa_b   = (const float*)d_in[9];
    const float* ua_w   = (const float*)d_in[10];
    const float* ua_b   = (const float*)d_in[11];
    const float* va_w   = (const float*)d_in[12];
    const float* va_b   = (const float*)d_in[13];
    float* out = (float*)d_out;

    float *xs, *gi, *ghp, *hs, *uk, *wq, *sc;
    cudaGetSymbolAddress((void**)&xs, g_xs);
    cudaGetSymbolAddress((void**)&gi, g_gi);
    cudaGetSymbolAddress((void**)&ghp, g_ghp);
    cudaGetSymbolAddress((void**)&hs, g_hs);
    cudaGetSymbolAddress((void**)&uk, g_uk);
    cudaGetSymbolAddress((void**)&wq, g_wq);
    cudaGetSymbolAddress((void**)&sc, g_sc);

    constexpr int LDSR = 36;
    const int smem_big = 2 * (128 + 128) * LDSR * 4;   // 73728 B
    const int smem_gru = 2 * (64 + 128) * LDSR * 4;    // 55296 B
    cudaFuncSetAttribute(k_gemm_tf32<128, 128, 4, 2>,
                         cudaFuncAttributeMaxDynamicSharedMemorySize, smem_big);
    cudaFuncSetAttribute(k_gru_step,
                         cudaFuncAttributeMaxDynamicSharedMemorySize, smem_gru);

    // front work (also resets GRU barrier counters)
    k_gather<<<(T * B * E + 255) / 256, 256>>>(target, emb, xs);

    // uk = enc @ ua_w^T + ua_b  [3200, 1024], K=2048
    k_gemm_tf32<128, 128, 4, 2><<<dim3(H / 128, (B * S) / 128), 256, smem_big>>>(
        enc, ua_w, ua_b, uk, B * S, H, H2);

    // gi = xs @ w_ih^T + b_ih   [640, 3072], K=512
    k_gemm_tf32<128, 128, 4, 2><<<dim3(H3 / 128, (T * B) / 128), 256, smem_big>>>(
        xs, w_ih, b_ih, gi, T * B, H3, E);

    // sequential GRU: one fused kernel per step
    const float* hprev = hidden;  // [B, H]
    for (int t = 0; t < T; t++) {
        k_gru_step<<<dim3(H3 / 128, 1, KSPLIT), 256, smem_gru>>>(
            hprev, w_hh, gi + (size_t)t * B * H3, b_hh, ghp,
            hs + (size_t)t * B * H, t);
        hprev = hs + (size_t)t * B * H;
    }

    // wq = hs @ wa_w^T + wa_b   [640, 1024], K=1024
    k_gemm_tf32<128, 128, 4, 2><<<dim3(H / 128, (T * B) / 128), 256, smem_big>>>(
        hs, wa_w, wa_b, wq, T * B, H, H);

    // additive attention scores + softmax
    k_scores<<<dim3(B, 4), 256>>>(wq, uk, va_w, va_b, sc);
    k_softmax<<<(T * B * 32 + 255) / 256, 256>>>(sc);

    // context + log_softmax into out[B, T, 2H] (reads enc directly)
    k_context<<<B, 256>>>(sc, enc, out);

    // h_last appended after out (tuple output flattened)
    if (out_size >= B * T * H2 + B * H)
        k_hlast<<<(B * H + 255) / 256, 256>>>(hs + (size_t)(T - 1) * B * H, out + B * T * H2);
}

// round 7
// speedup vs baseline: 1.0869x; 1.0869x over previous
#include <cuda_runtime.h>
#include <math.h>

// Problem dims (fixed by the reference)
namespace cfg {
constexpr int V = 32000, E = 512, H = 1024, S = 50, B = 64, T = 10;
constexpr int H2 = 2 * H, H3 = 3 * H;
constexpr int KSPLIT = 8;   // split-K for GRU gh GEMM (round-5 proven)
}
using namespace cfg;

// ---------------- device scratch (no allocations allowed) ----------------
__device__ float g_gi[T * B * H3];         // emb[dec_in] @ w_ih^T + b_ih  [T*B, 3H]
__device__ float g_ghp[KSPLIT * B * H3];   // split-K partials of h @ w_hh^T
__device__ float g_hs[T * B * H];          // GRU hidden states    [T, B, H]
__device__ float g_uk[B * S * H];          // enc @ ua_w^T + ua_b, rows in (s*B+b) order
__device__ float g_wq[T * B * H];          // hs @ wa_w^T + wa_b   [T*B, H]
__device__ float g_sc[T * B * S];          // raw scores           [T*B, S]

// ---------------- small intrinsics ----------------
__device__ __forceinline__ float tanha(float x) {
    float y;
    asm("tanh.approx.f32 %0, %1;" : "=f"(y) : "f"(x));
    return y;
}
// RNA round-to-nearest for tf32 (matches cvt.rna numerics on these magnitudes)
__device__ __forceinline__ unsigned rna(float f) {
    return __float_as_uint(f) + 0x1000u;
}
__device__ __forceinline__ void mma8(float* c, const unsigned* a, const unsigned* b) {
    asm volatile(
        "mma.sync.aligned.m16n8k8.row.col.f32.tf32.tf32.f32 "
        "{%0,%1,%2,%3}, {%4,%5,%6,%7}, {%8,%9}, {%0,%1,%2,%3};"
        : "+f"(c[0]), "+f"(c[1]), "+f"(c[2]), "+f"(c[3])
        : "r"(a[0]), "r"(a[1]), "r"(a[2]), "r"(a[3]), "r"(b[0]), "r"(b[1]));
}
__device__ __forceinline__ void cp16(float* smem_dst, const float* gptr) {
    unsigned s = (unsigned)__cvta_generic_to_shared(smem_dst);
    asm volatile("cp.async.cg.shared.global [%0], [%1], 16;\n" :: "r"(s), "l"(gptr));
}

// ---------------- tf32 tensor-core GEMM (cp.async double-buffered) ---------
// C[m][n] = (bias?bias[n]:0) + sum_{k in [z*klen, z*klen+klen)} A[m][k]*W[n][k]
// A [M,K], W [N,K] row-major. blockIdx.z = K-split slice; output at C + z*M*N.
// If GATHER: row m of A is emb[dec_in(m)] where dec_in(m) = (t==0?0:target[b*T+t-1]),
// t = m/B, b = m%B (A is then the embedding table, K=E).
template <int BM, int BN, int WM, int WN, bool GATHER>
__global__ void __launch_bounds__(WM * WN * 32, 2)
k_gemm_tf32(const float* __restrict__ A, const float* __restrict__ W,
            const float* __restrict__ bias, float* __restrict__ C,
            int M, int N, int K, int klen, const int* __restrict__ target) {
    constexpr int BK = 32;
    constexpr int NT = WM * WN * 32;
    constexpr int TM = BM / WM;
    constexpr int TN = BN / WN;
    constexpr int MM = TM / 16;
    constexpr int MN = TN / 8;
    constexpr int LDSR = BK + 4;
    constexpr int A_LD = BM * (BK / 4) / NT;
    constexpr int B_LD = BN * (BK / 4) / NT;

    extern __shared__ float sm[];
    float* Asm = sm;                      // [2][BM*LDSR]
    float* Bsm = sm + 2 * BM * LDSR;      // [2][BN*LDSR]

    const int tid = threadIdx.x;
    const int warp = tid >> 5, lane = tid & 31;
    const int wm = warp / WN, wn = warp % WN;
    const int g = lane >> 2, tg = lane & 3;
    const int bm = blockIdx.y * BM, bn = blockIdx.x * BN;
    const int kstart = blockIdx.z * klen;
    C += (size_t)blockIdx.z * M * N;

    // precompute per-thread source pointers / smem offsets (fixed over K loop)
    const float* abase[A_LD];
    const float* bbase[B_LD];
    int aoff[A_LD], boff[B_LD];
#pragma unroll
    for (int i = 0; i < A_LD; i++) {
        int idx = tid + i * NT;
        int r = idx >> 3, kq = idx & 7;
        int m = bm + r;
        const float* ar;
        if (GATHER) {
            int t = m / B, b = m % B;
            int tok = (t == 0) ? 0 : target[b * T + (t - 1)];
            ar = A + (size_t)tok * K;
        } else {
            ar = A + (size_t)m * K;
        }
        abase[i] = ar + kstart + kq * 4;
        aoff[i] = r * LDSR + kq * 4;
    }
#pragma unroll
    for (int i = 0; i < B_LD; i++) {
        int idx = tid + i * NT;
        int r = idx >> 3, kq = idx & 7;
        bbase[i] = W + (size_t)(bn + r) * K + kstart + kq * 4;
        boff[i] = r * LDSR + kq * 4;
    }

    float acc[MM][MN][4];
#pragma unroll
    for (int im = 0; im < MM; im++)
#pragma unroll
        for (int in = 0; in < MN; in++)
#pragma unroll
            for (int q = 0; q < 4; q++) acc[im][in][q] = 0.f;

    auto issue = [&](int k0, int buf) {
        float* as = Asm + buf * BM * LDSR;
        float* bs = Bsm + buf * BN * LDSR;
#pragma unroll
        for (int i = 0; i < A_LD; i++) cp16(as + aoff[i], abase[i] + k0);
#pragma unroll
        for (int i = 0; i < B_LD; i++) cp16(bs + boff[i], bbase[i] + k0);
        asm volatile("cp.async.commit_group;\n" ::);
    };

    issue(0, 0);
    const int KT = klen / BK;
    for (int kt = 0; kt < KT; kt++) {
        if (kt + 1 < KT) {
            issue((kt + 1) * BK, (kt + 1) & 1);
            asm volatile("cp.async.wait_group 1;\n" ::);
        } else {
            asm volatile("cp.async.wait_group 0;\n" ::);
        }
        __syncthreads();

        const float* as = Asm + (kt & 1) * BM * LDSR;
        const float* bs = Bsm + (kt & 1) * BN * LDSR;
#pragma unroll
        for (int ks = 0; ks < 4; ks++) {
            const int kk = ks * 8;
            unsigned af[MM][4], bf[MN][2];
#pragma unroll
            for (int im = 0; im < MM; im++) {
                int m0 = wm * TM + im * 16;
                af[im][0] = rna(as[(m0 + g) * LDSR + kk + tg]);
                af[im][1] = rna(as[(m0 + 8 + g) * LDSR + kk + tg]);
                af[im][2] = rna(as[(m0 + g) * LDSR + kk + 4 + tg]);
                af[im][3] = rna(as[(m0 + 8 + g) * LDSR + kk + 4 + tg]);
            }
#pragma unroll
            for (int in = 0; in < MN; in++) {
                int n0 = wn * TN + in * 8;
                bf[in][0] = rna(bs[(n0 + g) * LDSR + kk + tg]);
                bf[in][1] = rna(bs[(n0 + g) * LDSR + kk + 4 + tg]);
            }
#pragma unroll
            for (int im = 0; im < MM; im++)
#pragma unroll
                for (int in = 0; in < MN; in++)
                    mma8(acc[im][in], af[im], bf[in]);
        }
        __syncthreads();
    }

    // epilogue: + bias (optional), write
#pragma unroll
    for (int im = 0; im < MM; im++) {
        int row0 = bm + wm * TM + im * 16 + g;
#pragma unroll
        for (int in = 0; in < MN; in++) {
            int col = bn + wn * TN + in * 8 + 2 * tg;
            float bx = 0.f, by = 0.f;
            if (bias) {
                float2 bb = *(const float2*)(bias + col);
                bx = bb.x; by = bb.y;
            }
            float* c = acc[im][in];
            *(float2*)(C + (size_t)row0 * N + col) = make_float2(c[0] + bx, c[1] + by);
            *(float2*)(C + (size_t)(row0 + 8) * N + col) = make_float2(c[2] + bx, c[3] + by);
        }
    }
}

// ---------------- elementwise / attention kernels ----------------

// reduce split-K partials of gh, add biases, apply GRU gates (accurate math).
__global__ void k_gru_red(const float* __restrict__ part, const float* __restrict__ gi,
                          const float* __restrict__ b_hh_, const float* __restrict__ hprev,
                          float* __restrict__ hnew) {
    int idx = blockIdx.x * 256 + threadIdx.x;
    if (idx >= B * H) return;
    int b = idx / H, j = idx % H;
    float hr = b_hh_[j], hz = b_hh_[H + j], hn = b_hh_[2 * H + j];
#pragma unroll
    for (int s = 0; s < KSPLIT; s++) {
        const float* p = part + (size_t)s * B * H3 + (size_t)b * H3;
        hr += p[j];
        hz += p[H + j];
        hn += p[2 * H + j];
    }
    const float* gib = gi + (size_t)b * H3;
    float ir = gib[j], iz = gib[H + j], in_ = gib[2 * H + j];
    float r = 1.f / (1.f + expf(-(ir + hr)));
    float z = 1.f / (1.f + expf(-(iz + hz)));
    float n = tanhf(in_ + r * hn);
    hnew[idx] = (1.f - z) * n + z * hprev[idx];
}

// scores: grid (B, 4); wq[T][H] staged in smem; uk rows are in (s*B+b) order.
__global__ void k_scores(const float* __restrict__ wq, const float* __restrict__ uk,
                         const float* __restrict__ va_w, const float* __restrict__ va_b,
                         float* __restrict__ scores) {
    __shared__ float wqs[T][H];  // 40 KB
    int b = blockIdx.x, q = blockIdx.y;
    int tid = threadIdx.x;
    for (int i = tid; i < T * H; i += 256) {
        wqs[0][i] = wq[(size_t)(i / H * B + b) * H + (i % H)];
    }
    __syncthreads();

    int warp = tid >> 5, lane = tid & 31;
    float vb = va_b[0];
    for (int s = q * 8 + warp; s < S; s += 32) {
        const float4* ukr = (const float4*)(uk + (size_t)(s * B + b) * H);
        const float4* vw = (const float4*)va_w;
        float acc[T];
#pragma unroll
        for (int t = 0; t < T; t++) acc[t] = 0.f;
#pragma unroll
        for (int i = 0; i < H / 128; i++) {
            float4 u = ukr[lane + i * 32];
            float4 v = vw[lane + i * 32];
#pragma unroll
            for (int t = 0; t < T; t++) {
                float4 w = *(const float4*)&wqs[t][(lane + i * 32) * 4];
                float a = acc[t];
                a = fmaf(v.x, tanha(w.x + u.x), a);
                a = fmaf(v.y, tanha(w.y + u.y), a);
                a = fmaf(v.z, tanha(w.z + u.z), a);
                a = fmaf(v.w, tanha(w.w + u.w), a);
                acc[t] = a;
            }
        }
#pragma unroll
        for (int t = 0; t < T; t++) {
#pragma unroll
            for (int o = 16; o; o >>= 1) acc[t] += __shfl_xor_sync(0xffffffffu, acc[t], o);
            if (lane == 0) scores[(size_t)(t * B + b) * S + s] = acc[t] + vb;
        }
    }
}

// softmax (in-smem) + context + log_softmax + h_last copy: one block per b.
__global__ void k_context(const float* __restrict__ scores,
                          const float* __restrict__ enc,
                          const float* __restrict__ hs_last,
                          float* __restrict__ out, int do_hlast) {
    int b = blockIdx.x;
    int tid = threadIdx.x;
    int warp = tid >> 5, lane = tid & 31;
    __shared__ float w[T][S];
    __shared__ float red[8];

    for (int i = tid; i < T * S; i += 256) {
        int t = i / S, s = i % S;
        w[t][s] = scores[(size_t)(t * B + b) * S + s];
    }
    __syncthreads();

    // softmax over S per row t (warps own rows)
    for (int t = warp; t < T; t += 8) {
        float v0 = (lane < S) ? w[t][lane] : -1e30f;
        float v1 = (lane + 32 < S) ? w[t][lane + 32] : -1e30f;
        float m = fmaxf(v0, v1);
#pragma unroll
        for (int o = 16; o; o >>= 1) m = fmaxf(m, __shfl_xor_sync(0xffffffffu, m, o));
        float e0 = (lane < S) ? expf(v0 - m) : 0.f;
        float e1 = (lane + 32 < S) ? expf(v1 - m) : 0.f;
        float sum = e0 + e1;
#pragma unroll
        for (int o = 16; o; o >>= 1) sum += __shfl_xor_sync(0xffffffffu, sum, o);
        float inv = 1.f / sum;
        if (lane < S) w[t][lane] = e0 * inv;
        if (lane + 32 < S) w[t][lane + 32] = e1 * inv;
    }
    __syncthreads();

    float c[T][8];
#pragma unroll
    for (int t = 0; t < T; t++)
#pragma unroll
        for (int i = 0; i < 8; i++) c[t][i] = 0.f;

    for (int s = 0; s < S; s++) {
        const float* kr = enc + (size_t)(s * B + b) * H2;
        float4 k0 = *(const float4*)(kr + tid * 8);
        float4 k1 = *(const float4*)(kr + tid * 8 + 4);
        float kv[8] = {k0.x, k0.y, k0.z, k0.w, k1.x, k1.y, k1.z, k1.w};
#pragma unroll
        for (int t = 0; t < T; t++) {
            float ws = w[t][s];
#pragma unroll
            for (int i = 0; i < 8; i++) c[t][i] = fmaf(ws, kv[i], c[t][i]);
        }
    }

    for (int t = 0; t < T; t++) {
        float m = c[t][0];
#pragma unroll
        for (int i = 1; i < 8; i++) m = fmaxf(m, c[t][i]);
#pragma unroll
        for (int o = 16; o; o >>= 1) m = fmaxf(m, __shfl_xor_sync(0xffffffffu, m, o));
        if (lane == 0) red[warp] = m;
        __syncthreads();
        if (tid == 0) {
            float mm = red[0];
            for (int i = 1; i < 8; i++) mm = fmaxf(mm, red[i]);
            red[0] = mm;
        }
        __syncthreads();
        m = red[0];
        __syncthreads();

        float sum = 0.f;
#pragma unroll
        for (int i = 0; i < 8; i++) sum += expf(c[t][i] - m);
#pragma unroll
        for (int o = 16; o; o >>= 1) sum += __shfl_xor_sync(0xffffffffu, sum, o);
        if (lane == 0) red[warp] = sum;
        __syncthreads();
        if (tid == 0) {
            float ss = 0.f;
            for (int i = 1; i < 8; i++) ss += red[i];
            red[0] += ss;
        }
        __syncthreads();
        float lse = m + logf(red[0]);
        __syncthreads();

        float* o_ = out + (size_t)(b * T + t) * H2 + tid * 8;
        *(float4*)o_ = make_float4(c[t][0] - lse, c[t][1] - lse, c[t][2] - lse, c[t][3] - lse);
        *(float4*)(o_ + 4) = make_float4(c[t][4] - lse, c[t][5] - lse, c[t][6] - lse, c[t][7] - lse);
    }

    // h_last slice for this batch row
    if (do_hlast) {
        float* dst = out + (size_t)B * T * H2 + (size_t)b * H;
        const float* src = hs_last + (size_t)b * H;
#pragma unroll
        for (int i = 0; i < H / 256; i++) dst[tid + i * 256] = src[tid + i * 256];
    }
}

// ---------------- launch (single default stream, deterministic) -------------
extern "C" void kernel_launch(void* const* d_in, const int* in_sizes, int n_in,
                              void* d_out, int out_size) {
    const float* enc    = (const float*)d_in[0];
    const float* hidden = (const float*)d_in[1];
    const int*   target = (const int*)d_in[2];
    const float* emb    = (const float*)d_in[3];
    const float* w_ih   = (const float*)d_in[4];
    const float* w_hh   = (const float*)d_in[5];
    const float* b_ih   = (const float*)d_in[6];
    const float* b_hh   = (const float*)d_in[7];
    const float* wa_w   = (const float*)d_in[8];
    const float* wa_b   = (const float*)d_in[9];
    const float* ua_w   = (const float*)d_in[10];
    const float* ua_b   = (const float*)d_in[11];
    const float* va_w   = (const float*)d_in[12];
    const float* va_b   = (const float*)d_in[13];
    float* out = (float*)d_out;

    float *gi, *ghp, *hs, *uk, *wq, *sc;
    cudaGetSymbolAddress((void**)&gi, g_gi);
    cudaGetSymbolAddress((void**)&ghp, g_ghp);
    cudaGetSymbolAddress((void**)&hs, g_hs);
    cudaGetSymbolAddress((void**)&uk, g_uk);
    cudaGetSymbolAddress((void**)&wq, g_wq);
    cudaGetSymbolAddress((void**)&sc, g_sc);

    constexpr int LDSR = 36;
    const int smem_big = 2 * (128 + 128) * LDSR * 4;   // 73728 B
    const int smem_gh  = 2 * (64 + 128) * LDSR * 4;    // 55296 B
    cudaFuncSetAttribute((const void*)k_gemm_tf32<128, 128, 4, 2, false>,
                         cudaFuncAttributeMaxDynamicSharedMemorySize, smem_big);
    cudaFuncSetAttribute((const void*)k_gemm_tf32<128, 128, 4, 2, true>,
                         cudaFuncAttributeMaxDynamicSharedMemorySize, smem_big);
    cudaFuncSetAttribute((const void*)k_gemm_tf32<64, 128, 2, 4, false>,
                         cudaFuncAttributeMaxDynamicSharedMemorySize, smem_gh);

    // gi = emb[dec_in] @ w_ih^T + b_ih   [640, 3072], K=512 (gather fused)
    k_gemm_tf32<128, 128, 4, 2, true><<<dim3(H3 / 128, (T * B) / 128), 256, smem_big>>>(
        emb, w_ih, b_ih, gi, T * B, H3, E, E, target);

    // uk = enc @ ua_w^T + ua_b  [3200, 1024], K=2048
    k_gemm_tf32<128, 128, 4, 2, false><<<dim3(H / 128, (B * S) / 128), 256, smem_big>>>(
        enc, ua_w, ua_b, uk, B * S, H, H2, H2, nullptr);

    // sequential GRU over T steps (split-K gh GEMM + fused reduce/gate)
    const float* hprev = hidden;  // [B, H]
    for (int t = 0; t < T; t++) {
        k_gemm_tf32<64, 128, 2, 4, false><<<dim3(H3 / 128, 1, KSPLIT), 256, smem_gh>>>(
            hprev, w_hh, nullptr, ghp, B, H3, H, H / KSPLIT, nullptr);
        k_gru_red<<<(B * H + 255) / 256, 256>>>(ghp, gi + (size_t)t * B * H3, b_hh,
                                                hprev, hs + (size_t)t * B * H);
        hprev = hs + (size_t)t * B * H;
    }

    // wq = hs @ wa_w^T + wa_b   [640, 1024], K=1024
    k_gemm_tf32<128, 128, 4, 2, false><<<dim3(H / 128, (T * B) / 128), 256, smem_big>>>(
        hs, wa_w, wa_b, wq, T * B, H, H, H, nullptr);

    // attention scores (raw), then fused softmax+context+log_softmax+h_last
    k_scores<<<dim3(B, 4), 256>>>(wq, uk, va_w, va_b, sc);

    int do_hlast = (out_size >= B * T * H2 + B * H) ? 1 : 0;
    k_context<<<B, 256>>>(sc, enc, hs + (size_t)(T - 1) * B * H, out, do_hlast);
}